// round 9
// baseline (speedup 1.0000x reference)
#include <cuda_runtime.h>
#include <cstdint>

typedef unsigned long long ull;

__device__ __forceinline__ ull pack2(float lo, float hi) {
    ull r; asm("mov.b64 %0, {%1, %2};" : "=l"(r) : "f"(lo), "f"(hi)); return r;
}
__device__ __forceinline__ void unpack2(ull v, float& lo, float& hi) {
    asm("mov.b64 {%0, %1}, %2;" : "=f"(lo), "=f"(hi) : "l"(v));
}
#define FMA2(acc, a, b) asm("fma.rn.f32x2 %0, %1, %2, %0;" : "+l"(acc) : "l"(a), "l"(b))

__device__ __forceinline__ float tanh_approx(float x) {
    float y; asm("tanh.approx.f32 %0, %1;" : "=f"(y) : "f"(x)); return y;
}
__device__ __forceinline__ float sigf(float x) {           // final output only
    return __fdividef(1.f, 1.f + __expf(-x));
}

// P[v][slot], slot-permuted: slot 4u+p holds gate row p*64+u.
// Sigmoid-gate slots (p != 2) are PRE-SCALED by 0.5.  (51.2 MB)
__device__ float g_P[50000 * 256];

// ---------------------------------------------------------------------------
// Kernel 1: per-vocab input transform; permuted slots, sigmoid rows x0.5.
// ---------------------------------------------------------------------------
__global__ __launch_bounds__(256)
void prep_kernel(const float* __restrict__ emb,
                 const float* __restrict__ w_ih0,
                 const float* __restrict__ b_ih0,
                 const float* __restrict__ b_hh0,
                 int V)
{
    const int E = 100;
    const int j = threadIdx.x;
    const int slot = 4 * (j & 63) + (j >> 6);
    const float scale = ((j >> 6) == 2) ? 1.f : 0.5f;

    ull w[50];
    {
        const ull* wp = reinterpret_cast<const ull*>(w_ih0 + (size_t)j * E);
#pragma unroll
        for (int k = 0; k < 50; k++) w[k] = wp[k];
    }
    const float bias = b_ih0[j] + b_hh0[j];

    __shared__ __align__(16) float es[4 * 100];

    for (int v0 = blockIdx.x * 4; v0 < V; v0 += gridDim.x * 4) {
        __syncthreads();
        int nload = min(4 * E, (V - v0) * E);
        for (int idx = j; idx < nload; idx += 256) es[idx] = emb[(size_t)v0 * E + idx];
        __syncthreads();

        ull acc0 = 0, acc1 = 0, acc2 = 0, acc3 = 0;
#pragma unroll
        for (int q = 0; q < 25; q++) {
            ulonglong2 h0 = *reinterpret_cast<const ulonglong2*>(&es[0 * 100 + q * 4]);
            ulonglong2 h1 = *reinterpret_cast<const ulonglong2*>(&es[1 * 100 + q * 4]);
            ulonglong2 h2 = *reinterpret_cast<const ulonglong2*>(&es[2 * 100 + q * 4]);
            ulonglong2 h3 = *reinterpret_cast<const ulonglong2*>(&es[3 * 100 + q * 4]);
            FMA2(acc0, w[2 * q], h0.x);  FMA2(acc0, w[2 * q + 1], h0.y);
            FMA2(acc1, w[2 * q], h1.x);  FMA2(acc1, w[2 * q + 1], h1.y);
            FMA2(acc2, w[2 * q], h2.x);  FMA2(acc2, w[2 * q + 1], h2.y);
            FMA2(acc3, w[2 * q], h3.x);  FMA2(acc3, w[2 * q + 1], h3.y);
        }
        ull accs[4] = {acc0, acc1, acc2, acc3};
#pragma unroll
        for (int r = 0; r < 4; r++) {
            if (v0 + r < V) {
                float lo, hi; unpack2(accs[r], lo, hi);
                g_P[(size_t)(v0 + r) * 256 + slot] = (lo + hi + bias) * scale;
            }
        }
    }
}

// ---------------------------------------------------------------------------
// Kernel 2: fused 2-layer LSTM scan; layer-1 one step behind; peeled
// prologue/epilogue; interior manually unrolled x2 with static buffers;
// sigmoid gates via pre-scaled weights (act = 0.5*tanh(acc)+0.5).
// ---------------------------------------------------------------------------
__global__ __launch_bounds__(256, 1)
void scan_kernel(const int*   __restrict__ x,
                 const float* __restrict__ w_hh0,
                 const float* __restrict__ w_ih1,
                 const float* __restrict__ w_hh1,
                 const float* __restrict__ b_ih1,
                 const float* __restrict__ b_hh1,
                 const float* __restrict__ fc_w,
                 const float* __restrict__ fc_b,
                 float* __restrict__ out,
                 int T)
{
    const int HH = 64;
    const int t_ = threadIdx.x;
    const int p  = t_ & 3;        // gate type 0=i 1=f 2=g 3=o
    const int u  = t_ >> 2;       // unit 0..63
    const int r  = p * 64 + u;    // original gate row
    const int b0 = blockIdx.x * 2;
    const bool is_g = (p == 2);

    __shared__ __align__(16) float hs[2][4][68];     // [buf][vec][unit], padded
    __shared__ __align__(16) float sact[4][260];     // [vec][slot 4u+p], padded
    __shared__ int sx[2][513];                       // +1 sentinel slot

    // Per-thread weights, pre-scaled for sigmoid gates.
    const float ws = is_g ? 1.f : 0.5f;
    ull w0[32], wi[32], wh[32];
    {
        const float* q0 = w_hh0 + (size_t)r * HH;
        const float* q1 = w_ih1 + (size_t)r * HH;
        const float* q2 = w_hh1 + (size_t)r * HH;
#pragma unroll
        for (int k = 0; k < 32; k++) {
            w0[k] = pack2(q0[2 * k] * ws, q0[2 * k + 1] * ws);
            wi[k] = pack2(q1[2 * k] * ws, q1[2 * k + 1] * ws);
            wh[k] = pack2(q2[2 * k] * ws, q2[2 * k + 1] * ws);
        }
    }
    const float bias1 = (b_ih1[r] + b_hh1[r]) * ws;

    for (int i = t_; i < T; i += 256) {
        sx[0][i] = x[(size_t)b0 * T + i];
        sx[1][i] = x[(size_t)(b0 + 1) * T + i];
    }
    if (t_ < 2) sx[t_][T] = 0;                       // sentinel
    for (int i = t_; i < 2 * 4 * 68; i += 256) ((float*)hs)[i] = 0.f;

    float cstate = 0.f;     // lane's cell state for its (layer,row) = vec p

    const float resmul = is_g ? 1.f : 0.5f;
    const float resadd = is_g ? 0.f : 0.5f;
    const float* csrc = &sact[p][4 * (unsigned)u];
    const int* sx0 = sx[0];
    const int* sx1 = sx[1];

    __syncthreads();

    float curP0 = g_P[(size_t)sx0[0] * 256 + t_];
    float curP1 = g_P[(size_t)sx1[0] * 256 + t_];

    // ================= prologue t = 0: layer0 only =================
    {
        float nP0 = g_P[(size_t)sx0[1] * 256 + t_];
        float nP1 = g_P[(size_t)sx1[1] * 256 + t_];
        sact[0][t_] = fmaf(tanh_approx(curP0), resmul, resadd);
        sact[1][t_] = fmaf(tanh_approx(curP1), resmul, resadd);
        __syncwarp();
        if (p < 2) {
            float4 g4 = *reinterpret_cast<const float4*>(csrc);
            cstate = g4.y * cstate + g4.x * g4.z;
            hs[1][p][u] = g4.w * tanh_approx(cstate);
        }
        curP0 = nP0; curP1 = nP1;
        __syncthreads();
    }

    // ================= interior t = 1..T-1, unrolled x2 =================
#define STEP(CUR, NXT, TN) do {                                               \
        float nP0 = g_P[(size_t)sx0[TN] * 256 + t_];                          \
        float nP1 = g_P[(size_t)sx1[TN] * 256 + t_];                          \
        const float* H = &hs[CUR][0][0];                                      \
        ull a0  = pack2(curP0, 0.f);                                          \
        ull a1  = pack2(curP1, 0.f);                                          \
        ull g1a = pack2(bias1, 0.f);                                          \
        ull g1b = pack2(bias1, 0.f);                                          \
        ull g1c = 0ull;                                                       \
        ull g1d = 0ull;                                                       \
        _Pragma("unroll")                                                     \
        for (int q = 0; q < 16; q++) {                                        \
            ulonglong2 u0 = *reinterpret_cast<const ulonglong2*>(H + 0 * 68 + q * 4); \
            ulonglong2 u1 = *reinterpret_cast<const ulonglong2*>(H + 1 * 68 + q * 4); \
            ulonglong2 v0 = *reinterpret_cast<const ulonglong2*>(H + 2 * 68 + q * 4); \
            ulonglong2 v1 = *reinterpret_cast<const ulonglong2*>(H + 3 * 68 + q * 4); \
            FMA2(a0,  w0[2 * q],     u0.x);                                   \
            FMA2(a1,  w0[2 * q],     u1.x);                                   \
            FMA2(g1a, wi[2 * q],     u0.x);                                   \
            FMA2(g1b, wi[2 * q],     u1.x);                                   \
            FMA2(g1c, wh[2 * q],     v0.x);                                   \
            FMA2(g1d, wh[2 * q],     v1.x);                                   \
            FMA2(a0,  w0[2 * q + 1], u0.y);                                   \
            FMA2(a1,  w0[2 * q + 1], u1.y);                                   \
            FMA2(g1a, wi[2 * q + 1], u0.y);                                   \
            FMA2(g1b, wi[2 * q + 1], u1.y);                                   \
            FMA2(g1c, wh[2 * q + 1], v0.y);                                   \
            FMA2(g1d, wh[2 * q + 1], v1.y);                                   \
        }                                                                     \
        {                                                                     \
            float lo, hi, lo2, hi2;                                           \
            unpack2(a0, lo, hi);  float s0 = lo + hi;                         \
            unpack2(a1, lo, hi);  float s1 = lo + hi;                         \
            unpack2(g1a, lo, hi); unpack2(g1c, lo2, hi2);                     \
            float v0 = (lo + hi) + (lo2 + hi2);                               \
            unpack2(g1b, lo, hi); unpack2(g1d, lo2, hi2);                     \
            float v1 = (lo + hi) + (lo2 + hi2);                               \
            sact[0][t_] = fmaf(tanh_approx(s0), resmul, resadd);              \
            sact[1][t_] = fmaf(tanh_approx(s1), resmul, resadd);              \
            sact[2][t_] = fmaf(tanh_approx(v0), resmul, resadd);              \
            sact[3][t_] = fmaf(tanh_approx(v1), resmul, resadd);              \
        }                                                                     \
        __syncwarp();                                                         \
        {                                                                     \
            float4 g4 = *reinterpret_cast<const float4*>(csrc);               \
            cstate = g4.y * cstate + g4.x * g4.z;                             \
            hs[NXT][p][u] = g4.w * tanh_approx(cstate);                       \
        }                                                                     \
        curP0 = nP0; curP1 = nP1;                                             \
        __syncthreads();                                                      \
    } while (0)

    int t = 1;
#pragma unroll 1
    for (; t + 1 < T; t += 2) {       // pairs (odd, even); T even => leftover
        STEP(1, 0, t + 1);
        STEP(0, 1, t + 2);
    }
    STEP(1, 0, T);                    // t = T-1 (odd); TN = T hits sentinel

#undef STEP

    // ================= epilogue t = T: layer1 only =================
    {
        const float* H = &hs[0][0][0];   // T even -> cur buffer is 0
        ull g1a = pack2(bias1, 0.f);
        ull g1b = pack2(bias1, 0.f);
        ull g1c = 0ull;
        ull g1d = 0ull;
#pragma unroll
        for (int q = 0; q < 16; q++) {
            ulonglong2 u0 = *reinterpret_cast<const ulonglong2*>(H + 0 * 68 + q * 4);
            ulonglong2 u1 = *reinterpret_cast<const ulonglong2*>(H + 1 * 68 + q * 4);
            ulonglong2 v0 = *reinterpret_cast<const ulonglong2*>(H + 2 * 68 + q * 4);
            ulonglong2 v1 = *reinterpret_cast<const ulonglong2*>(H + 3 * 68 + q * 4);
            FMA2(g1a, wi[2 * q],     u0.x);
            FMA2(g1b, wi[2 * q],     u1.x);
            FMA2(g1c, wh[2 * q],     v0.x);
            FMA2(g1d, wh[2 * q],     v1.x);
            FMA2(g1a, wi[2 * q + 1], u0.y);
            FMA2(g1b, wi[2 * q + 1], u1.y);
            FMA2(g1c, wh[2 * q + 1], v0.y);
            FMA2(g1d, wh[2 * q + 1], v1.y);
        }
        {
            float lo, hi, lo2, hi2;
            unpack2(g1a, lo, hi); unpack2(g1c, lo2, hi2);
            float v0 = (lo + hi) + (lo2 + hi2);
            unpack2(g1b, lo, hi); unpack2(g1d, lo2, hi2);
            float v1 = (lo + hi) + (lo2 + hi2);
            sact[2][t_] = fmaf(tanh_approx(v0), resmul, resadd);
            sact[3][t_] = fmaf(tanh_approx(v1), resmul, resadd);
        }
        __syncwarp();
        if (p >= 2) {
            float4 g4 = *reinterpret_cast<const float4*>(csrc);
            cstate = g4.y * cstate + g4.x * g4.z;
            hs[1][p][u] = g4.w * tanh_approx(cstate);   // h1(T-1)
        }
        __syncthreads();
    }

    // ---- final: out[b] = sigmoid(relu(h1(T-1)) . fc_w + fc_b) ----
    if (t_ < 2) {
        const float* hf = &hs[1][2 + t_][0];
        float sacc = fc_b[0];
#pragma unroll
        for (int uu = 0; uu < HH; uu++)
            sacc += fmaxf(hf[uu], 0.f) * fc_w[uu];
        out[b0 + t_] = sigf(sacc);
    }
}

// ---------------------------------------------------------------------------
// Launch
// ---------------------------------------------------------------------------
extern "C" void kernel_launch(void* const* d_in, const int* in_sizes, int n_in,
                              void* d_out, int out_size)
{
    const int*   x     = (const int*)  d_in[0];
    const float* emb   = (const float*)d_in[1];
    const float* w_ih0 = (const float*)d_in[2];
    const float* w_hh0 = (const float*)d_in[3];
    const float* b_ih0 = (const float*)d_in[4];
    const float* b_hh0 = (const float*)d_in[5];
    const float* w_ih1 = (const float*)d_in[6];
    const float* w_hh1 = (const float*)d_in[7];
    const float* b_ih1 = (const float*)d_in[8];
    const float* b_hh1 = (const float*)d_in[9];
    const float* fc_w  = (const float*)d_in[10];
    const float* fc_b  = (const float*)d_in[11];
    float* out = (float*)d_out;

    const int B = out_size;              // 256
    const int T = in_sizes[0] / B;       // 512 (even)
    const int E = in_sizes[2] / 256;     // 100
    const int V = in_sizes[1] / E;       // 50000

    (void)n_in; (void)E;

    prep_kernel<<<296, 256>>>(emb, w_ih0, b_ih0, b_hh0, V);
    scan_kernel<<<B / 2, 256>>>(x, w_hh0, w_ih1, w_hh1, b_ih1, b_hh1,
                                fc_w, fc_b, out, T);
}